// round 15
// baseline (speedup 1.0000x reference)
#include <cuda_runtime.h>
#include <cuda_fp16.h>
#include <cstdint>

#define BMAX 131072
#define NC   8

__device__ uint32_t g_qwh[(size_t)BMAX * 256];
__device__ uint2    g_wn[(size_t)BMAX * 128];
__device__ uint2    g_b0[2 * 8 * 128 * 8];
__device__ uint2    g_bn[4 * 2 * 128 * 8];
__device__ uint2    g_b3[16 * 128 * 8];

static cudaStream_t g_s1, g_s2;
static cudaEvent_t g_evA[NC], g_evN[NC], g_evP, g_evEnd;
namespace {
struct SInit {
    SInit() {
        cudaStreamCreateWithFlags(&g_s1, cudaStreamNonBlocking);
        cudaStreamCreateWithFlags(&g_s2, cudaStreamNonBlocking);
        for (int i = 0; i < NC; i++) {
            cudaEventCreateWithFlags(&g_evA[i], cudaEventDisableTiming);
            cudaEventCreateWithFlags(&g_evN[i], cudaEventDisableTiming);
        }
        cudaEventCreateWithFlags(&g_evP, cudaEventDisableTiming);
        cudaEventCreateWithFlags(&g_evEnd, cudaEventDisableTiming);
    }
};
SInit g_sinit;
}

__device__ __forceinline__ uint32_t smem_u32(const void* p) {
    uint32_t a;
    asm("{ .reg .u64 t; cvta.to.shared.u64 t, %1; cvt.u32.u64 %0, t; }" : "=r"(a) : "l"(p));
    return a;
}
__device__ __forceinline__ uint32_t hpack(float a, float b) {
    __half2 h = __floats2half2_rn(a, b);
    return *reinterpret_cast<uint32_t*>(&h);
}
__device__ __forceinline__ uint4 mk4h(float a, float b, float c, float d) {
    uint4 u;
    u.x = hpack(a, b); u.y = hpack(c, d);
    __half2 hx = *reinterpret_cast<__half2*>(&u.x);
    __half2 hy = *reinterpret_cast<__half2*>(&u.y);
    u.z = hpack(a - __half2float(__low2half(hx)), b - __half2float(__high2half(hx)));
    u.w = hpack(c - __half2float(__low2half(hy)), d - __half2float(__high2half(hy)));
    return u;
}
__device__ __forceinline__ void mma_fp16(float* c, uint32_t a0, uint32_t a1,
                                         uint32_t a2, uint32_t a3, uint32_t b0, uint32_t b1) {
    asm volatile(
        "mma.sync.aligned.m16n8k16.row.col.f32.f16.f16.f32 "
        "{%0,%1,%2,%3},{%4,%5,%6,%7},{%8,%9},{%0,%1,%2,%3};\n"
        : "+f"(c[0]), "+f"(c[1]), "+f"(c[2]), "+f"(c[3])
        : "r"(a0), "r"(a1), "r"(a2), "r"(a3), "r"(b0), "r"(b1));
}
__device__ __forceinline__ float4 ldcs4(const float4* p) {
    float4 v;
    asm volatile("ld.global.cs.v4.f32 {%0,%1,%2,%3}, [%4];"
                 : "=f"(v.x), "=f"(v.y), "=f"(v.z), "=f"(v.w) : "l"(p));
    return v;
}
__device__ __forceinline__ uint2 ldcs2(const uint2* p) {
    uint2 v;
    asm volatile("ld.global.cs.v2.u32 {%0,%1}, [%2];" : "=r"(v.x), "=r"(v.y) : "l"(p));
    return v;
}
#define CP16(dst, src) \
    asm volatile("cp.async.cg.shared.global [%0], [%1], 16;\n" :: "r"(dst), "l"(src) : "memory")
#define CPCOMMIT() asm volatile("cp.async.commit_group;\n" ::: "memory")
#define CPWAIT0()  asm volatile("cp.async.wait_group 0;\n" ::: "memory")

// ---------- preps ----------
__global__ void k_prep_b0(const float* __restrict__ Wc, const float* __restrict__ Wco) {
    int idx = blockIdx.x * 256 + threadIdx.x;
    if (idx >= 2 * 8 * 128 * 8) return;
    int j = idx & 7, n = (idx >> 3) & 127, kh = (idx >> 10) & 7, nt = idx >> 13;
    int ks = j >> 2, tg = j & 3;
    int k0 = kh * 32 + ks * 16 + 2 * tg;
    const float* s = nt ? Wco : Wc;
    g_b0[idx] = make_uint2(hpack(s[n * 256 + k0], s[n * 256 + k0 + 1]),
                           hpack(s[n * 256 + k0 + 8], s[n * 256 + k0 + 9]));
}
__global__ void k_prep_bn(const float* __restrict__ Wn) {
    int idx = blockIdx.x * 256 + threadIdx.x;
    if (idx >= 4 * 2 * 128 * 8) return;
    int j = idx & 7, n = (idx >> 3) & 127, kh = (idx >> 10) & 1, nt = idx >> 11;
    int col = nt * 128 + n;
    int h = col >> 8, j2 = col & 255;
    int ks = j >> 2, tg = j & 3;
    int a0 = kh * 32 + ks * 16 + 2 * tg;
    g_bn[idx] = make_uint2(
        hpack(Wn[(h * 64 + a0) * 256 + j2], Wn[(h * 64 + a0 + 1) * 256 + j2]),
        hpack(Wn[(h * 64 + a0 + 8) * 256 + j2], Wn[(h * 64 + a0 + 9) * 256 + j2]));
}
#define P3_WO   0
#define P3_WV   (128 * 132 * 4)
#define P3_PART (P3_WV + 128 * 36 * 4)
#define P3_SMEM (P3_PART + 2 * 128 * 32 * 4)
__global__ void k_prep_b3(const float* __restrict__ Wo, const float* __restrict__ Wv) {
    extern __shared__ __align__(16) char sm3[];
    float* Wo_t = (float*)(sm3 + P3_WO);
    float* Wv_s = (float*)(sm3 + P3_WV);
    float* part = (float*)(sm3 + P3_PART);
    const int kh = blockIdx.x, h = kh >> 3, iwin = (kh * 32) & 255, tid = threadIdx.x;
    for (int i = tid; i < 4096; i += 256) {
        int n = i >> 5, d4 = i & 31;
        float4 x = *(const float4*)(Wo + n * 256 + h * 128 + d4 * 4);
        Wo_t[(d4 * 4 + 0) * 132 + n] = x.x; Wo_t[(d4 * 4 + 1) * 132 + n] = x.y;
        Wo_t[(d4 * 4 + 2) * 132 + n] = x.z; Wo_t[(d4 * 4 + 3) * 132 + n] = x.w;
    }
    for (int i = tid; i < 1024; i += 256) {
        int d = i >> 3, i4 = i & 7;
        *(float4*)&Wv_s[d * 36 + i4 * 4] = *(const float4*)(Wv + (h * 128 + d) * 256 + iwin + i4 * 4);
    }
    __syncthreads();
    {
        int n = tid & 127, hf = tid >> 7;
        float acc[32];
#pragma unroll
        for (int i = 0; i < 32; i++) acc[i] = 0.f;
        for (int d = hf * 64; d < hf * 64 + 64; d++) {
            float wo = Wo_t[d * 132 + n];
#pragma unroll
            for (int i4 = 0; i4 < 8; i4++) {
                float4 wv = *(const float4*)&Wv_s[d * 36 + i4 * 4];
                acc[i4 * 4 + 0] = fmaf(wo, wv.x, acc[i4 * 4 + 0]);
                acc[i4 * 4 + 1] = fmaf(wo, wv.y, acc[i4 * 4 + 1]);
                acc[i4 * 4 + 2] = fmaf(wo, wv.z, acc[i4 * 4 + 2]);
                acc[i4 * 4 + 3] = fmaf(wo, wv.w, acc[i4 * 4 + 3]);
            }
        }
#pragma unroll
        for (int i = 0; i < 32; i++) part[(hf * 128 + n) * 32 + i] = acc[i];
    }
    __syncthreads();
    for (int o = tid; o < 1024; o += 256) {
        int j = o & 7, n = o >> 3;
        int ks = j >> 2, tg = j & 3;
        int i0 = ks * 16 + 2 * tg;
        float v0 = part[n * 32 + i0] + part[(128 + n) * 32 + i0];
        float v1 = part[n * 32 + i0 + 1] + part[(128 + n) * 32 + i0 + 1];
        float v2 = part[n * 32 + i0 + 8] + part[(128 + n) * 32 + i0 + 8];
        float v3 = part[n * 32 + i0 + 9] + part[(128 + n) * 32 + i0 + 9];
        g_b3[kh * 1024 + n * 8 + j] = make_uint2(hpack(v0, v1), hpack(v2, v3));
    }
}

// ---------- k_front0: t (1-pass) then qW (1-pass, fp16 out) ----------
#define F0SMEM 73728
#define A1P(st, m, j) (smem + (st) * 12288 + (m) * 96 + (j) * 8)
#define B0P(st, n, j) (smem + 24576 + (st) * 12288 + (n) * 96 + (j) * 8)
#define TPP(p, m, j)  (smem + (p) * 12288 + (m) * 96 + (j) * 8)
#define G1P(kh, n, j) (smem + 49152 + (kh) * 12288 + (n) * 96 + (j) * 8)

__global__ __launch_bounds__(256) void k_front0(const float* __restrict__ Ain, int row0) {
    extern __shared__ __align__(16) char smem[];
    const int tid = threadIdx.x, lid = tid & 31, w = tid >> 5;
    const int g = lid >> 2, tg = lid & 3;
    const int wm = (w & 1) * 64, wnn = (w >> 1) * 32;
    const int bm = blockIdx.x;
    const float* Ab = Ain + (size_t)(row0 + bm * 128) * 256;
    const int arow = tid >> 1, aks = tid & 1;
    float4 f[2][4];
    auto loadA = [&](int kh, int sl) {
        const float* b = Ab + (size_t)arow * 256 + kh * 32 + aks * 16;
#pragma unroll
        for (int q = 0; q < 4; q++) f[sl][q] = *(const float4*)(b + q * 4);
    };
    auto sts1 = [&](int kh) {
        int st = kh & 1, sl = kh & 1;
        float4 f0 = f[sl][0], f1 = f[sl][1], f2 = f[sl][2], f3 = f[sl][3];
        *(uint2*)A1P(st, arow, aks * 4 + 0) = make_uint2(hpack(f0.x, f0.y), hpack(f2.x, f2.y));
        *(uint2*)A1P(st, arow, aks * 4 + 1) = make_uint2(hpack(f0.z, f0.w), hpack(f2.z, f2.w));
        *(uint2*)A1P(st, arow, aks * 4 + 2) = make_uint2(hpack(f1.x, f1.y), hpack(f3.x, f3.y));
        *(uint2*)A1P(st, arow, aks * 4 + 3) = make_uint2(hpack(f1.z, f1.w), hpack(f3.z, f3.w));
    };
    auto cpB0 = [&](int kh) {
        int st = kh & 1;
        const char* src = (const char*)g_b0 + (size_t)kh * 8192;
#pragma unroll
        for (int i = 0; i < 2; i++) {
            int v = tid + 256 * i;
            CP16(smem_u32(B0P(st, v >> 2, (v & 3) * 2)), src + v * 16);
        }
    };

    float acc[4][4][4];
#pragma unroll
    for (int i = 0; i < 4; i++)
#pragma unroll
        for (int jn = 0; jn < 4; jn++)
#pragma unroll
            for (int r = 0; r < 4; r++) acc[i][jn][r] = 0.f;

    cpB0(0); CPCOMMIT(); loadA(0, 0); sts1(0); loadA(1, 1);
    for (int kh = 0; kh < 8; kh++) {
        CPWAIT0(); __syncthreads();
        if (kh < 7) { cpB0(kh + 1); CPCOMMIT(); sts1(kh + 1); }
        if (kh < 6) loadA(kh + 2, kh & 1);
        int cur = kh & 1;
#pragma unroll
        for (int ks = 0; ks < 2; ks++) {
            uint2 V[4];
#pragma unroll
            for (int nt = 0; nt < 4; nt++)
                V[nt] = *(uint2*)B0P(cur, wnn + nt * 8 + g, ks * 4 + tg);
#pragma unroll
            for (int mt = 0; mt < 4; mt++) {
                uint2 U0 = *(uint2*)A1P(cur, wm + mt * 16 + g, ks * 4 + tg);
                uint2 U1 = *(uint2*)A1P(cur, wm + mt * 16 + g + 8, ks * 4 + tg);
#pragma unroll
                for (int nt = 0; nt < 4; nt++)
                    mma_fp16(acc[mt][nt], U0.x, U1.x, U0.y, U1.y, V[nt].x, V[nt].y);
            }
        }
    }
    __syncthreads();

#pragma unroll
    for (int mt = 0; mt < 4; mt++)
#pragma unroll
        for (int nt = 0; nt < 4; nt++) {
            int row = wm + mt * 16 + g, coll = wnn + nt * 8 + 2 * tg;
            int p = coll >> 5, ww = coll & 31;
            int ks2 = ww >> 4, w16 = ww & 15, hf = w16 >> 3, t2 = (w16 & 7) >> 1;
            int s = ks2 * 4 + t2;
            *(uint32_t*)(TPP(p, row, s) + hf * 4) = hpack(acc[mt][nt][0], acc[mt][nt][1]);
            *(uint32_t*)(TPP(p, row + 8, s) + hf * 4) = hpack(acc[mt][nt][2], acc[mt][nt][3]);
        }
    __syncthreads();

    auto cpG1 = [&](int nt2) {
        const char* src = (const char*)g_bn + (size_t)nt2 * 16384;
#pragma unroll
        for (int i = 0; i < 4; i++) {
            int v = tid + 256 * i;
            int kh = v >> 9, r = v & 511;
            CP16(smem_u32(G1P(kh, r >> 2, (r & 3) * 2)), src + v * 16);
        }
    };
    cpG1(0); CPCOMMIT();
    for (int nt2 = 0; nt2 < 4; nt2++) {
        CPWAIT0(); __syncthreads();
        int h = nt2 >> 1;
        float a2[4][4][4];
#pragma unroll
        for (int i = 0; i < 4; i++)
#pragma unroll
            for (int jn = 0; jn < 4; jn++)
#pragma unroll
                for (int r = 0; r < 4; r++) a2[i][jn][r] = 0.f;
#pragma unroll
        for (int kh2 = 0; kh2 < 2; kh2++) {
            int p = 2 * h + kh2;
#pragma unroll
            for (int ks = 0; ks < 2; ks++) {
                uint2 V[4];
#pragma unroll
                for (int n2 = 0; n2 < 4; n2++)
                    V[n2] = *(uint2*)G1P(kh2, wnn + n2 * 8 + g, ks * 4 + tg);
#pragma unroll
                for (int mt = 0; mt < 4; mt++) {
                    uint2 U0 = *(uint2*)TPP(p, wm + mt * 16 + g, ks * 4 + tg);
                    uint2 U1 = *(uint2*)TPP(p, wm + mt * 16 + g + 8, ks * 4 + tg);
#pragma unroll
                    for (int n2 = 0; n2 < 4; n2++)
                        mma_fp16(a2[mt][n2], U0.x, U1.x, U0.y, U1.y, V[n2].x, V[n2].y);
                }
            }
        }
        __syncthreads();
        if (nt2 < 3) { cpG1(nt2 + 1); CPCOMMIT(); }
#pragma unroll
        for (int mt = 0; mt < 4; mt++)
#pragma unroll
            for (int n2 = 0; n2 < 4; n2++) {
                const float* c = a2[mt][n2];
                int row = row0 + bm * 128 + wm + mt * 16 + g;
                int col = nt2 * 128 + wnn + n2 * 8 + 2 * tg;
                g_qwh[(size_t)row * 256 + (col >> 1)] = hpack(c[0], c[1]);
                g_qwh[(size_t)(row + 8) * 256 + (col >> 1)] = hpack(c[2], c[3]);
            }
    }
}

// ---------- k_cout: center_out = center @ Wco^T, 2-pass, whole B ----------
#define COSMEM 73728
#define A2P(st, m, j) (smem + (st) * 24576 + (m) * 192 + (j) * 16)
#define B1P(st, n, j) (smem + 49152 + (st) * 12288 + (n) * 96 + (j) * 8)

__global__ __launch_bounds__(256) void k_cout(const float* __restrict__ Ain,
                                              float* __restrict__ dOut) {
    extern __shared__ __align__(16) char smem[];
    const int tid = threadIdx.x, lid = tid & 31, w = tid >> 5;
    const int g = lid >> 2, tg = lid & 3;
    const int wm = (w & 1) * 64, wnn = (w >> 1) * 32;
    const int bm = blockIdx.x;
    const float* Ab = Ain + (size_t)bm * 128 * 256;
    const int arow = tid >> 1, aks = tid & 1;
    float4 f[2][4];
    auto loadA = [&](int kh, int sl) {
        const float* b = Ab + (size_t)arow * 256 + kh * 32 + aks * 16;
#pragma unroll
        for (int q = 0; q < 4; q++) f[sl][q] = *(const float4*)(b + q * 4);
    };
    auto sts2 = [&](int kh) {
        int st = kh & 1, sl = kh & 1;
        float4 f0 = f[sl][0], f1 = f[sl][1], f2 = f[sl][2], f3 = f[sl][3];
        *(uint4*)A2P(st, arow, aks * 4 + 0) = mk4h(f0.x, f0.y, f2.x, f2.y);
        *(uint4*)A2P(st, arow, aks * 4 + 1) = mk4h(f0.z, f0.w, f2.z, f2.w);
        *(uint4*)A2P(st, arow, aks * 4 + 2) = mk4h(f1.x, f1.y, f3.x, f3.y);
        *(uint4*)A2P(st, arow, aks * 4 + 3) = mk4h(f1.z, f1.w, f3.z, f3.w);
    };
    auto cpB1 = [&](int kh) {
        int st = kh & 1;
        const char* src = (const char*)g_b0 + 65536 + (size_t)kh * 8192;
#pragma unroll
        for (int i = 0; i < 2; i++) {
            int v = tid + 256 * i;
            CP16(smem_u32(B1P(st, v >> 2, (v & 3) * 2)), src + v * 16);
        }
    };
    float acc[4][4][4];
#pragma unroll
    for (int i = 0; i < 4; i++)
#pragma unroll
        for (int jn = 0; jn < 4; jn++)
#pragma unroll
            for (int r = 0; r < 4; r++) acc[i][jn][r] = 0.f;
    cpB1(0); CPCOMMIT(); loadA(0, 0); sts2(0); loadA(1, 1);
    for (int kh = 0; kh < 8; kh++) {
        CPWAIT0(); __syncthreads();
        if (kh < 7) { cpB1(kh + 1); CPCOMMIT(); sts2(kh + 1); }
        if (kh < 6) loadA(kh + 2, kh & 1);
        int cur = kh & 1;
#pragma unroll
        for (int ks = 0; ks < 2; ks++) {
            uint2 V[4];
#pragma unroll
            for (int nt = 0; nt < 4; nt++)
                V[nt] = *(uint2*)B1P(cur, wnn + nt * 8 + g, ks * 4 + tg);
#pragma unroll
            for (int mt = 0; mt < 4; mt++) {
                uint4 U0 = *(uint4*)A2P(cur, wm + mt * 16 + g, ks * 4 + tg);
                uint4 U1 = *(uint4*)A2P(cur, wm + mt * 16 + g + 8, ks * 4 + tg);
#pragma unroll
                for (int nt = 0; nt < 4; nt++) {
                    mma_fp16(acc[mt][nt], U0.x, U1.x, U0.y, U1.y, V[nt].x, V[nt].y);
                    mma_fp16(acc[mt][nt], U0.z, U1.z, U0.w, U1.w, V[nt].x, V[nt].y);
                }
            }
        }
    }
#pragma unroll
    for (int mt = 0; mt < 4; mt++)
#pragma unroll
        for (int nt = 0; nt < 4; nt++) {
            const float* c = acc[mt][nt];
            int row = bm * 128 + wm + mt * 16 + g;
            int coll = wnn + nt * 8 + 2 * tg;
            *(float2*)(dOut + (size_t)row * 256 + coll) = make_float2(c[0], c[1]);
            *(float2*)(dOut + (size_t)(row + 8) * 256 + coll) = make_float2(c[2], c[3]);
        }
}

// ---------- k_attn (R11-proven form, 12 blocks/SM) ----------
__global__ __launch_bounds__(128, 12) void k_attn(const float* __restrict__ nb_g,
                                                  const float* __restrict__ ew_g, int b0) {
    const int b = b0 + blockIdx.x;
    __shared__ uint2 nbh[16][68];
    __shared__ float qw_s[512];
    __shared__ float ews[16];
    __shared__ float sc[2][16];
    __shared__ float at[2][16];
    const int tid = threadIdx.x;
    const int k = tid >> 3, s = tid & 7;
    {
        uint2 u = ldcs2((const uint2*)(g_qwh + (size_t)b * 256) + tid);
        float2 a = __half22float2(*reinterpret_cast<__half2*>(&u.x));
        float2 bb = __half22float2(*reinterpret_cast<__half2*>(&u.y));
        *(float4*)&qw_s[tid * 4] = make_float4(a.x, a.y, bb.x, bb.y);
    }
    if (tid < 16) ews[tid] = ew_g[(size_t)b * 16 + tid];
    __syncthreads();
    const float4* nb4 = (const float4*)(nb_g + (size_t)b * 4096);
    float p0 = 0.f, p1 = 0.f;
#pragma unroll
    for (int j = 0; j < 8; j++) {
        int c4 = s + 8 * j;
        float4 x = ldcs4(nb4 + k * 64 + c4);
        nbh[k][c4] = make_uint2(hpack(x.x, x.y), hpack(x.z, x.w));
        float4 q0 = *(const float4*)&qw_s[c4 * 4];
        float4 q1 = *(const float4*)&qw_s[256 + c4 * 4];
        p0 = fmaf(x.x, q0.x, p0); p0 = fmaf(x.y, q0.y, p0);
        p0 = fmaf(x.z, q0.z, p0); p0 = fmaf(x.w, q0.w, p0);
        p1 = fmaf(x.x, q1.x, p1); p1 = fmaf(x.y, q1.y, p1);
        p1 = fmaf(x.z, q1.z, p1); p1 = fmaf(x.w, q1.w, p1);
    }
#pragma unroll
    for (int o = 1; o <= 4; o <<= 1) {
        p0 += __shfl_xor_sync(0xffffffffu, p0, o);
        p1 += __shfl_xor_sync(0xffffffffu, p1, o);
    }
    if (s == 0) {
        sc[0][k] = p0 * 0.125f + ews[k];
        sc[1][k] = p1 * 0.125f + ews[k];
    }
    __syncthreads();
    if (tid < 32) {
        int hh = tid >> 4, kk = tid & 15;
        float v = sc[hh][kk];
        float m = v;
#pragma unroll
        for (int o = 8; o >= 1; o >>= 1)
            m = fmaxf(m, __shfl_xor_sync(0xffffffffu, m, o));
        float e = __expf(v - m);
        float sum = e;
#pragma unroll
        for (int o = 8; o >= 1; o >>= 1)
            sum += __shfl_xor_sync(0xffffffffu, sum, o);
        at[hh][kk] = e / sum;
    }
    __syncthreads();
    {
        int hh = tid >> 6, c2 = tid & 63;
        float4 acc = make_float4(0.f, 0.f, 0.f, 0.f);
#pragma unroll
        for (int kk = 0; kk < 16; kk++) {
            float wgt = at[hh][kk];
            uint2 u = nbh[kk][c2];
            float2 f0 = __half22float2(*reinterpret_cast<__half2*>(&u.x));
            float2 f1 = __half22float2(*reinterpret_cast<__half2*>(&u.y));
            acc.x = fmaf(wgt, f0.x, acc.x);
            acc.y = fmaf(wgt, f0.y, acc.y);
            acc.z = fmaf(wgt, f1.x, acc.z);
            acc.w = fmaf(wgt, f1.y, acc.w);
        }
        g_wn[(size_t)b * 128 + tid] = make_uint2(hpack(acc.x, acc.y), hpack(acc.z, acc.w));
    }
}

// ---------- k_ctx ----------
#define CSMEM 61440
#define CAP(st, m, wd) (smem + (st) * 30720 + (m) * 144 + (wd) * 4)
#define CBP(st, n, j)  (smem + (st) * 30720 + 18432 + (n) * 96 + (j) * 8)

__global__ __launch_bounds__(256) void k_ctx(float* __restrict__ dOut, int row0) {
    extern __shared__ __align__(16) char smem[];
    const int tid = threadIdx.x, lid = tid & 31, w = tid >> 5;
    const int g = lid >> 2, tg = lid & 3;
    const int wm = (w & 1) * 64, wnn = (w >> 1) * 32;
    const int bm = blockIdx.x;
    auto cpA = [&](int kh) {
        int st = kh & 1;
        const char* src = (const char*)g_wn + (size_t)(row0 + bm * 128) * 1024 + kh * 64;
#pragma unroll
        for (int i = 0; i < 2; i++) {
            int v = tid + 256 * i;
            CP16(smem_u32(CAP(st, v >> 2, (v & 3) * 4)), src + (size_t)(v >> 2) * 1024 + (v & 3) * 16);
        }
    };
    auto cpB = [&](int kh) {
        int st = kh & 1;
        const char* src = (const char*)g_b3 + (size_t)kh * 8192;
#pragma unroll
        for (int i = 0; i < 2; i++) {
            int v = tid + 256 * i;
            CP16(smem_u32(CBP(st, v >> 2, (v & 3) * 2)), src + v * 16);
        }
    };
    cpA(0); cpB(0); CPCOMMIT();
    float acc[4][4][4];
#pragma unroll
    for (int i = 0; i < 4; i++)
#pragma unroll
        for (int jn = 0; jn < 4; jn++)
#pragma unroll
            for (int r = 0; r < 4; r++) acc[i][jn][r] = 0.f;
    for (int kh = 0; kh < 16; kh++) {
        CPWAIT0(); __syncthreads();
        if (kh < 15) { cpA(kh + 1); cpB(kh + 1); CPCOMMIT(); }
        int cur = kh & 1;
#pragma unroll
        for (int ks = 0; ks < 2; ks++) {
            uint2 V[4];
#pragma unroll
            for (int nt = 0; nt < 4; nt++)
                V[nt] = *(uint2*)CBP(cur, wnn + nt * 8 + g, ks * 4 + tg);
#pragma unroll
            for (int mt = 0; mt < 4; mt++) {
                int m = wm + mt * 16 + g, w0 = ks * 8 + tg;
                uint32_t a0 = *(uint32_t*)CAP(cur, m, w0);
                uint32_t a2 = *(uint32_t*)CAP(cur, m, w0 + 4);
                uint32_t a1 = *(uint32_t*)CAP(cur, m + 8, w0);
                uint32_t a3 = *(uint32_t*)CAP(cur, m + 8, w0 + 4);
#pragma unroll
                for (int nt = 0; nt < 4; nt++)
                    mma_fp16(acc[mt][nt], a0, a1, a2, a3, V[nt].x, V[nt].y);
            }
        }
    }
#pragma unroll
    for (int mt = 0; mt < 4; mt++)
#pragma unroll
        for (int nt = 0; nt < 4; nt++) {
            const float* c = acc[mt][nt];
            int row = row0 + bm * 128 + wm + mt * 16 + g;
            int col = 128 + wnn + nt * 8 + 2 * tg;
            *(float2*)(dOut + (size_t)row * 256 + col) = make_float2(c[0], c[1]);
            *(float2*)(dOut + (size_t)(row + 8) * 256 + col) = make_float2(c[2], c[3]);
        }
}

// ---------- launch ----------
extern "C" void kernel_launch(void* const* d_in, const int* in_sizes, int n_in,
                              void* d_out, int out_size) {
    const float* center = (const float*)d_in[0];
    const float* nbr    = (const float*)d_in[1];
    const float* ew     = (const float*)d_in[2];
    const float* Wc     = (const float*)d_in[3];
    const float* Wn     = (const float*)d_in[4];
    const float* Wv     = (const float*)d_in[5];
    const float* Wo     = (const float*)d_in[6];
    const float* Wco    = (const float*)d_in[7];
    float* out = (float*)d_out;
    const int B = in_sizes[0] / 256;
    const int CH = B / NC;

    cudaFuncSetAttribute(k_front0, cudaFuncAttributeMaxDynamicSharedMemorySize, F0SMEM);
    cudaFuncSetAttribute(k_cout, cudaFuncAttributeMaxDynamicSharedMemorySize, COSMEM);
    cudaFuncSetAttribute(k_ctx, cudaFuncAttributeMaxDynamicSharedMemorySize, CSMEM);
    cudaFuncSetAttribute(k_prep_b3, cudaFuncAttributeMaxDynamicSharedMemorySize, P3_SMEM);

    k_prep_b0<<<64, 256>>>(Wc, Wco);
    k_prep_bn<<<32, 256>>>(Wn);
    k_prep_b3<<<16, 256, P3_SMEM>>>(Wo, Wv);
    cudaEventRecord(g_evP, 0);

    cudaStreamWaitEvent(g_s2, g_evP, 0);
    k_cout<<<B / 128, 256, COSMEM, g_s2>>>(center, out);

    for (int c = 0; c < NC; c++) {
        const int row0 = c * CH;
        k_front0<<<CH / 128, 256, F0SMEM>>>(center, row0);
        cudaEventRecord(g_evA[c], 0);
        cudaStreamWaitEvent(g_s1, g_evA[c], 0);
        k_attn<<<CH, 128, 0, g_s1>>>(nbr, ew, row0);
        cudaEventRecord(g_evN[c], g_s1);
        cudaStreamWaitEvent(g_s2, g_evN[c], 0);
        k_ctx<<<CH / 128, 256, CSMEM, g_s2>>>(out, row0);
    }
    cudaEventRecord(g_evEnd, g_s2);
    cudaStreamWaitEvent(0, g_evEnd, 0);
}

// round 16
// speedup vs baseline: 1.1488x; 1.1488x over previous
#include <cuda_runtime.h>
#include <cuda_fp16.h>
#include <cstdint>

#define BMAX 131072
#define NC   4

__device__ uint32_t g_qwh[(size_t)BMAX * 256];
__device__ uint2    g_wn[(size_t)BMAX * 128];
__device__ uint2    g_b0[2 * 8 * 128 * 8];
__device__ uint2    g_bn[4 * 2 * 128 * 8];
__device__ uint2    g_b3[16 * 128 * 8];

static cudaStream_t g_s1, g_s2;
static cudaEvent_t g_evA[NC], g_evN[NC], g_evP, g_evEnd;
namespace {
struct SInit {
    SInit() {
        cudaStreamCreateWithFlags(&g_s1, cudaStreamNonBlocking);
        cudaStreamCreateWithFlags(&g_s2, cudaStreamNonBlocking);
        for (int i = 0; i < NC; i++) {
            cudaEventCreateWithFlags(&g_evA[i], cudaEventDisableTiming);
            cudaEventCreateWithFlags(&g_evN[i], cudaEventDisableTiming);
        }
        cudaEventCreateWithFlags(&g_evP, cudaEventDisableTiming);
        cudaEventCreateWithFlags(&g_evEnd, cudaEventDisableTiming);
    }
};
SInit g_sinit;
}

__device__ __forceinline__ uint32_t smem_u32(const void* p) {
    uint32_t a;
    asm("{ .reg .u64 t; cvta.to.shared.u64 t, %1; cvt.u32.u64 %0, t; }" : "=r"(a) : "l"(p));
    return a;
}
__device__ __forceinline__ uint32_t hpack(float a, float b) {
    __half2 h = __floats2half2_rn(a, b);
    return *reinterpret_cast<uint32_t*>(&h);
}
__device__ __forceinline__ uint4 mk4h(float a, float b, float c, float d) {
    uint4 u;
    u.x = hpack(a, b); u.y = hpack(c, d);
    __half2 hx = *reinterpret_cast<__half2*>(&u.x);
    __half2 hy = *reinterpret_cast<__half2*>(&u.y);
    u.z = hpack(a - __half2float(__low2half(hx)), b - __half2float(__high2half(hx)));
    u.w = hpack(c - __half2float(__low2half(hy)), d - __half2float(__high2half(hy)));
    return u;
}
__device__ __forceinline__ void mma_fp16(float* c, uint32_t a0, uint32_t a1,
                                         uint32_t a2, uint32_t a3, uint32_t b0, uint32_t b1) {
    asm volatile(
        "mma.sync.aligned.m16n8k16.row.col.f32.f16.f16.f32 "
        "{%0,%1,%2,%3},{%4,%5,%6,%7},{%8,%9},{%0,%1,%2,%3};\n"
        : "+f"(c[0]), "+f"(c[1]), "+f"(c[2]), "+f"(c[3])
        : "r"(a0), "r"(a1), "r"(a2), "r"(a3), "r"(b0), "r"(b1));
}
#define CP16(dst, src) \
    asm volatile("cp.async.cg.shared.global [%0], [%1], 16;\n" :: "r"(dst), "l"(src) : "memory")
#define CPCOMMIT() asm volatile("cp.async.commit_group;\n" ::: "memory")
#define CPWAIT0()  asm volatile("cp.async.wait_group 0;\n" ::: "memory")

// ---------- preps ----------
__global__ void k_prep_b0(const float* __restrict__ Wc, const float* __restrict__ Wco) {
    int idx = blockIdx.x * 256 + threadIdx.x;
    if (idx >= 2 * 8 * 128 * 8) return;
    int j = idx & 7, n = (idx >> 3) & 127, kh = (idx >> 10) & 7, nt = idx >> 13;
    int ks = j >> 2, tg = j & 3;
    int k0 = kh * 32 + ks * 16 + 2 * tg;
    const float* s = nt ? Wco : Wc;
    g_b0[idx] = make_uint2(hpack(s[n * 256 + k0], s[n * 256 + k0 + 1]),
                           hpack(s[n * 256 + k0 + 8], s[n * 256 + k0 + 9]));
}
__global__ void k_prep_bn(const float* __restrict__ Wn) {
    int idx = blockIdx.x * 256 + threadIdx.x;
    if (idx >= 4 * 2 * 128 * 8) return;
    int j = idx & 7, n = (idx >> 3) & 127, kh = (idx >> 10) & 1, nt = idx >> 11;
    int col = nt * 128 + n;
    int h = col >> 8, j2 = col & 255;
    int ks = j >> 2, tg = j & 3;
    int a0 = kh * 32 + ks * 16 + 2 * tg;
    g_bn[idx] = make_uint2(
        hpack(Wn[(h * 64 + a0) * 256 + j2], Wn[(h * 64 + a0 + 1) * 256 + j2]),
        hpack(Wn[(h * 64 + a0 + 8) * 256 + j2], Wn[(h * 64 + a0 + 9) * 256 + j2]));
}
#define P3_WO   0
#define P3_WV   (128 * 132 * 4)
#define P3_PART (P3_WV + 128 * 36 * 4)
#define P3_SMEM (P3_PART + 2 * 128 * 32 * 4)
__global__ void k_prep_b3(const float* __restrict__ Wo, const float* __restrict__ Wv) {
    extern __shared__ __align__(16) char sm3[];
    float* Wo_t = (float*)(sm3 + P3_WO);
    float* Wv_s = (float*)(sm3 + P3_WV);
    float* part = (float*)(sm3 + P3_PART);
    const int kh = blockIdx.x, h = kh >> 3, iwin = (kh * 32) & 255, tid = threadIdx.x;
    for (int i = tid; i < 4096; i += 256) {
        int n = i >> 5, d4 = i & 31;
        float4 x = *(const float4*)(Wo + n * 256 + h * 128 + d4 * 4);
        Wo_t[(d4 * 4 + 0) * 132 + n] = x.x; Wo_t[(d4 * 4 + 1) * 132 + n] = x.y;
        Wo_t[(d4 * 4 + 2) * 132 + n] = x.z; Wo_t[(d4 * 4 + 3) * 132 + n] = x.w;
    }
    for (int i = tid; i < 1024; i += 256) {
        int d = i >> 3, i4 = i & 7;
        *(float4*)&Wv_s[d * 36 + i4 * 4] = *(const float4*)(Wv + (h * 128 + d) * 256 + iwin + i4 * 4);
    }
    __syncthreads();
    {
        int n = tid & 127, hf = tid >> 7;
        float acc[32];
#pragma unroll
        for (int i = 0; i < 32; i++) acc[i] = 0.f;
        for (int d = hf * 64; d < hf * 64 + 64; d++) {
            float wo = Wo_t[d * 132 + n];
#pragma unroll
            for (int i4 = 0; i4 < 8; i4++) {
                float4 wv = *(const float4*)&Wv_s[d * 36 + i4 * 4];
                acc[i4 * 4 + 0] = fmaf(wo, wv.x, acc[i4 * 4 + 0]);
                acc[i4 * 4 + 1] = fmaf(wo, wv.y, acc[i4 * 4 + 1]);
                acc[i4 * 4 + 2] = fmaf(wo, wv.z, acc[i4 * 4 + 2]);
                acc[i4 * 4 + 3] = fmaf(wo, wv.w, acc[i4 * 4 + 3]);
            }
        }
#pragma unroll
        for (int i = 0; i < 32; i++) part[(hf * 128 + n) * 32 + i] = acc[i];
    }
    __syncthreads();
    for (int o = tid; o < 1024; o += 256) {
        int j = o & 7, n = o >> 3;
        int ks = j >> 2, tg = j & 3;
        int i0 = ks * 16 + 2 * tg;
        float v0 = part[n * 32 + i0] + part[(128 + n) * 32 + i0];
        float v1 = part[n * 32 + i0 + 1] + part[(128 + n) * 32 + i0 + 1];
        float v2 = part[n * 32 + i0 + 8] + part[(128 + n) * 32 + i0 + 8];
        float v3 = part[n * 32 + i0 + 9] + part[(128 + n) * 32 + i0 + 9];
        g_b3[kh * 1024 + n * 8 + j] = make_uint2(hpack(v0, v1), hpack(v2, v3));
    }
}

// ---------- k_front0: t (1-pass) then qW (1-pass, fp16 out) ----------
#define F0SMEM 73728
#define A1P(st, m, j) (smem + (st) * 12288 + (m) * 96 + (j) * 8)
#define B0P(st, n, j) (smem + 24576 + (st) * 12288 + (n) * 96 + (j) * 8)
#define TPP(p, m, j)  (smem + (p) * 12288 + (m) * 96 + (j) * 8)
#define G1P(kh, n, j) (smem + 49152 + (kh) * 12288 + (n) * 96 + (j) * 8)

__global__ __launch_bounds__(256) void k_front0(const float* __restrict__ Ain, int row0) {
    extern __shared__ __align__(16) char smem[];
    const int tid = threadIdx.x, lid = tid & 31, w = tid >> 5;
    const int g = lid >> 2, tg = lid & 3;
    const int wm = (w & 1) * 64, wnn = (w >> 1) * 32;
    const int bm = blockIdx.x;
    const float* Ab = Ain + (size_t)(row0 + bm * 128) * 256;
    const int arow = tid >> 1, aks = tid & 1;
    float4 f[2][4];
    auto loadA = [&](int kh, int sl) {
        const float* b = Ab + (size_t)arow * 256 + kh * 32 + aks * 16;
#pragma unroll
        for (int q = 0; q < 4; q++) f[sl][q] = *(const float4*)(b + q * 4);
    };
    auto sts1 = [&](int kh) {
        int st = kh & 1, sl = kh & 1;
        float4 f0 = f[sl][0], f1 = f[sl][1], f2 = f[sl][2], f3 = f[sl][3];
        *(uint2*)A1P(st, arow, aks * 4 + 0) = make_uint2(hpack(f0.x, f0.y), hpack(f2.x, f2.y));
        *(uint2*)A1P(st, arow, aks * 4 + 1) = make_uint2(hpack(f0.z, f0.w), hpack(f2.z, f2.w));
        *(uint2*)A1P(st, arow, aks * 4 + 2) = make_uint2(hpack(f1.x, f1.y), hpack(f3.x, f3.y));
        *(uint2*)A1P(st, arow, aks * 4 + 3) = make_uint2(hpack(f1.z, f1.w), hpack(f3.z, f3.w));
    };
    auto cpB0 = [&](int kh) {
        int st = kh & 1;
        const char* src = (const char*)g_b0 + (size_t)kh * 8192;
#pragma unroll
        for (int i = 0; i < 2; i++) {
            int v = tid + 256 * i;
            CP16(smem_u32(B0P(st, v >> 2, (v & 3) * 2)), src + v * 16);
        }
    };

    float acc[4][4][4];
#pragma unroll
    for (int i = 0; i < 4; i++)
#pragma unroll
        for (int jn = 0; jn < 4; jn++)
#pragma unroll
            for (int r = 0; r < 4; r++) acc[i][jn][r] = 0.f;

    cpB0(0); CPCOMMIT(); loadA(0, 0); sts1(0); loadA(1, 1);
    for (int kh = 0; kh < 8; kh++) {
        CPWAIT0(); __syncthreads();
        if (kh < 7) { cpB0(kh + 1); CPCOMMIT(); sts1(kh + 1); }
        if (kh < 6) loadA(kh + 2, kh & 1);
        int cur = kh & 1;
#pragma unroll
        for (int ks = 0; ks < 2; ks++) {
            uint2 V[4];
#pragma unroll
            for (int nt = 0; nt < 4; nt++)
                V[nt] = *(uint2*)B0P(cur, wnn + nt * 8 + g, ks * 4 + tg);
#pragma unroll
            for (int mt = 0; mt < 4; mt++) {
                uint2 U0 = *(uint2*)A1P(cur, wm + mt * 16 + g, ks * 4 + tg);
                uint2 U1 = *(uint2*)A1P(cur, wm + mt * 16 + g + 8, ks * 4 + tg);
#pragma unroll
                for (int nt = 0; nt < 4; nt++)
                    mma_fp16(acc[mt][nt], U0.x, U1.x, U0.y, U1.y, V[nt].x, V[nt].y);
            }
        }
    }
    __syncthreads();

#pragma unroll
    for (int mt = 0; mt < 4; mt++)
#pragma unroll
        for (int nt = 0; nt < 4; nt++) {
            int row = wm + mt * 16 + g, coll = wnn + nt * 8 + 2 * tg;
            int p = coll >> 5, ww = coll & 31;
            int ks2 = ww >> 4, w16 = ww & 15, hf = w16 >> 3, t2 = (w16 & 7) >> 1;
            int s = ks2 * 4 + t2;
            *(uint32_t*)(TPP(p, row, s) + hf * 4) = hpack(acc[mt][nt][0], acc[mt][nt][1]);
            *(uint32_t*)(TPP(p, row + 8, s) + hf * 4) = hpack(acc[mt][nt][2], acc[mt][nt][3]);
        }
    __syncthreads();

    auto cpG1 = [&](int nt2) {
        const char* src = (const char*)g_bn + (size_t)nt2 * 16384;
#pragma unroll
        for (int i = 0; i < 4; i++) {
            int v = tid + 256 * i;
            int kh = v >> 9, r = v & 511;
            CP16(smem_u32(G1P(kh, r >> 2, (r & 3) * 2)), src + v * 16);
        }
    };
    cpG1(0); CPCOMMIT();
    for (int nt2 = 0; nt2 < 4; nt2++) {
        CPWAIT0(); __syncthreads();
        int h = nt2 >> 1;
        float a2[4][4][4];
#pragma unroll
        for (int i = 0; i < 4; i++)
#pragma unroll
            for (int jn = 0; jn < 4; jn++)
#pragma unroll
                for (int r = 0; r < 4; r++) a2[i][jn][r] = 0.f;
#pragma unroll
        for (int kh2 = 0; kh2 < 2; kh2++) {
            int p = 2 * h + kh2;
#pragma unroll
            for (int ks = 0; ks < 2; ks++) {
                uint2 V[4];
#pragma unroll
                for (int n2 = 0; n2 < 4; n2++)
                    V[n2] = *(uint2*)G1P(kh2, wnn + n2 * 8 + g, ks * 4 + tg);
#pragma unroll
                for (int mt = 0; mt < 4; mt++) {
                    uint2 U0 = *(uint2*)TPP(p, wm + mt * 16 + g, ks * 4 + tg);
                    uint2 U1 = *(uint2*)TPP(p, wm + mt * 16 + g + 8, ks * 4 + tg);
#pragma unroll
                    for (int n2 = 0; n2 < 4; n2++)
                        mma_fp16(a2[mt][n2], U0.x, U1.x, U0.y, U1.y, V[n2].x, V[n2].y);
                }
            }
        }
        __syncthreads();
        if (nt2 < 3) { cpG1(nt2 + 1); CPCOMMIT(); }
#pragma unroll
        for (int mt = 0; mt < 4; mt++)
#pragma unroll
            for (int n2 = 0; n2 < 4; n2++) {
                const float* c = a2[mt][n2];
                int row = row0 + bm * 128 + wm + mt * 16 + g;
                int col = nt2 * 128 + wnn + n2 * 8 + 2 * tg;
                g_qwh[(size_t)row * 256 + (col >> 1)] = hpack(c[0], c[1]);
                g_qwh[(size_t)(row + 8) * 256 + (col >> 1)] = hpack(c[2], c[3]);
            }
    }
}

// ---------- k_cout: center_out = center @ Wco^T, 2-pass, whole B ----------
#define COSMEM 73728
#define A2P(st, m, j) (smem + (st) * 24576 + (m) * 192 + (j) * 16)
#define B1P(st, n, j) (smem + 49152 + (st) * 12288 + (n) * 96 + (j) * 8)

__global__ __launch_bounds__(256) void k_cout(const float* __restrict__ Ain,
                                              float* __restrict__ dOut) {
    extern __shared__ __align__(16) char smem[];
    const int tid = threadIdx.x, lid = tid & 31, w = tid >> 5;
    const int g = lid >> 2, tg = lid & 3;
    const int wm = (w & 1) * 64, wnn = (w >> 1) * 32;
    const int bm = blockIdx.x;
    const float* Ab = Ain + (size_t)bm * 128 * 256;
    const int arow = tid >> 1, aks = tid & 1;
    float4 f[2][4];
    auto loadA = [&](int kh, int sl) {
        const float* b = Ab + (size_t)arow * 256 + kh * 32 + aks * 16;
#pragma unroll
        for (int q = 0; q < 4; q++) f[sl][q] = *(const float4*)(b + q * 4);
    };
    auto sts2 = [&](int kh) {
        int st = kh & 1, sl = kh & 1;
        float4 f0 = f[sl][0], f1 = f[sl][1], f2 = f[sl][2], f3 = f[sl][3];
        *(uint4*)A2P(st, arow, aks * 4 + 0) = mk4h(f0.x, f0.y, f2.x, f2.y);
        *(uint4*)A2P(st, arow, aks * 4 + 1) = mk4h(f0.z, f0.w, f2.z, f2.w);
        *(uint4*)A2P(st, arow, aks * 4 + 2) = mk4h(f1.x, f1.y, f3.x, f3.y);
        *(uint4*)A2P(st, arow, aks * 4 + 3) = mk4h(f1.z, f1.w, f3.z, f3.w);
    };
    auto cpB1 = [&](int kh) {
        int st = kh & 1;
        const char* src = (const char*)g_b0 + 65536 + (size_t)kh * 8192;
#pragma unroll
        for (int i = 0; i < 2; i++) {
            int v = tid + 256 * i;
            CP16(smem_u32(B1P(st, v >> 2, (v & 3) * 2)), src + v * 16);
        }
    };
    float acc[4][4][4];
#pragma unroll
    for (int i = 0; i < 4; i++)
#pragma unroll
        for (int jn = 0; jn < 4; jn++)
#pragma unroll
            for (int r = 0; r < 4; r++) acc[i][jn][r] = 0.f;
    cpB1(0); CPCOMMIT(); loadA(0, 0); sts2(0); loadA(1, 1);
    for (int kh = 0; kh < 8; kh++) {
        CPWAIT0(); __syncthreads();
        if (kh < 7) { cpB1(kh + 1); CPCOMMIT(); sts2(kh + 1); }
        if (kh < 6) loadA(kh + 2, kh & 1);
        int cur = kh & 1;
#pragma unroll
        for (int ks = 0; ks < 2; ks++) {
            uint2 V[4];
#pragma unroll
            for (int nt = 0; nt < 4; nt++)
                V[nt] = *(uint2*)B1P(cur, wnn + nt * 8 + g, ks * 4 + tg);
#pragma unroll
            for (int mt = 0; mt < 4; mt++) {
                uint4 U0 = *(uint4*)A2P(cur, wm + mt * 16 + g, ks * 4 + tg);
                uint4 U1 = *(uint4*)A2P(cur, wm + mt * 16 + g + 8, ks * 4 + tg);
#pragma unroll
                for (int nt = 0; nt < 4; nt++) {
                    mma_fp16(acc[mt][nt], U0.x, U1.x, U0.y, U1.y, V[nt].x, V[nt].y);
                    mma_fp16(acc[mt][nt], U0.z, U1.z, U0.w, U1.w, V[nt].x, V[nt].y);
                }
            }
        }
    }
#pragma unroll
    for (int mt = 0; mt < 4; mt++)
#pragma unroll
        for (int nt = 0; nt < 4; nt++) {
            const float* c = acc[mt][nt];
            int row = bm * 128 + wm + mt * 16 + g;
            int coll = wnn + nt * 8 + 2 * tg;
            *(float2*)(dOut + (size_t)row * 256 + coll) = make_float2(c[0], c[1]);
            *(float2*)(dOut + (size_t)(row + 8) * 256 + coll) = make_float2(c[2], c[3]);
        }
}

// ---------- k_attn (R11-proven form) ----------
__global__ __launch_bounds__(128) void k_attn(const float* __restrict__ nb_g,
                                              const float* __restrict__ ew_g, int b0) {
    const int b = b0 + blockIdx.x;
    __shared__ uint2 nbh[16][68];
    __shared__ float qw_s[512];
    __shared__ float ews[16];
    __shared__ float sc[2][16];
    __shared__ float at[2][16];
    const int tid = threadIdx.x;
    const int k = tid >> 3, s = tid & 7;
    {
        uint2 u = ((const uint2*)(g_qwh + (size_t)b * 256))[tid];
        float2 a = __half22float2(*reinterpret_cast<__half2*>(&u.x));
        float2 bb = __half22float2(*reinterpret_cast<__half2*>(&u.y));
        *(float4*)&qw_s[tid * 4] = make_float4(a.x, a.y, bb.x, bb.y);
    }
    if (tid < 16) ews[tid] = ew_g[(size_t)b * 16 + tid];
    __syncthreads();
    const float4* nb4 = (const float4*)(nb_g + (size_t)b * 4096);
    float p0 = 0.f, p1 = 0.f;
#pragma unroll
    for (int j = 0; j < 8; j++) {
        int c4 = s + 8 * j;
        float4 x = nb4[k * 64 + c4];
        nbh[k][c4] = make_uint2(hpack(x.x, x.y), hpack(x.z, x.w));
        float4 q0 = *(const float4*)&qw_s[c4 * 4];
        float4 q1 = *(const float4*)&qw_s[256 + c4 * 4];
        p0 = fmaf(x.x, q0.x, p0); p0 = fmaf(x.y, q0.y, p0);
        p0 = fmaf(x.z, q0.z, p0); p0 = fmaf(x.w, q0.w, p0);
        p1 = fmaf(x.x, q1.x, p1); p1 = fmaf(x.y, q1.y, p1);
        p1 = fmaf(x.z, q1.z, p1); p1 = fmaf(x.w, q1.w, p1);
    }
#pragma unroll
    for (int o = 1; o <= 4; o <<= 1) {
        p0 += __shfl_xor_sync(0xffffffffu, p0, o);
        p1 += __shfl_xor_sync(0xffffffffu, p1, o);
    }
    if (s == 0) {
        sc[0][k] = p0 * 0.125f + ews[k];
        sc[1][k] = p1 * 0.125f + ews[k];
    }
    __syncthreads();
    if (tid < 32) {
        int hh = tid >> 4, kk = tid & 15;
        float v = sc[hh][kk];
        float m = v;
#pragma unroll
        for (int o = 8; o >= 1; o >>= 1)
            m = fmaxf(m, __shfl_xor_sync(0xffffffffu, m, o));
        float e = __expf(v - m);
        float sum = e;
#pragma unroll
        for (int o = 8; o >= 1; o >>= 1)
            sum += __shfl_xor_sync(0xffffffffu, sum, o);
        at[hh][kk] = e / sum;
    }
    __syncthreads();
    {
        int hh = tid >> 6, c2 = tid & 63;
        float4 acc = make_float4(0.f, 0.f, 0.f, 0.f);
#pragma unroll
        for (int kk = 0; kk < 16; kk++) {
            float wgt = at[hh][kk];
            uint2 u = nbh[kk][c2];
            float2 f0 = __half22float2(*reinterpret_cast<__half2*>(&u.x));
            float2 f1 = __half22float2(*reinterpret_cast<__half2*>(&u.y));
            acc.x = fmaf(wgt, f0.x, acc.x);
            acc.y = fmaf(wgt, f0.y, acc.y);
            acc.z = fmaf(wgt, f1.x, acc.z);
            acc.w = fmaf(wgt, f1.y, acc.w);
        }
        g_wn[(size_t)b * 128 + tid] = make_uint2(hpack(acc.x, acc.y), hpack(acc.z, acc.w));
    }
}

// ---------- k_ctx ----------
#define CSMEM 61440
#define CAP(st, m, wd) (smem + (st) * 30720 + (m) * 144 + (wd) * 4)
#define CBP(st, n, j)  (smem + (st) * 30720 + 18432 + (n) * 96 + (j) * 8)

__global__ __launch_bounds__(256) void k_ctx(float* __restrict__ dOut, int row0) {
    extern __shared__ __align__(16) char smem[];
    const int tid = threadIdx.x, lid = tid & 31, w = tid >> 5;
    const int g = lid >> 2, tg = lid & 3;
    const int wm = (w & 1) * 64, wnn = (w >> 1) * 32;
    const int bm = blockIdx.x;
    auto cpA = [&](int kh) {
        int st = kh & 1;
        const char* src = (const char*)g_wn + (size_t)(row0 + bm * 128) * 1024 + kh * 64;
#pragma unroll
        for (int i = 0; i < 2; i++) {
            int v = tid + 256 * i;
            CP16(smem_u32(CAP(st, v >> 2, (v & 3) * 4)), src + (size_t)(v >> 2) * 1024 + (v & 3) * 16);
        }
    };
    auto cpB = [&](int kh) {
        int st = kh & 1;
        const char* src = (const char*)g_b3 + (size_t)kh * 8192;
#pragma unroll
        for (int i = 0; i < 2; i++) {
            int v = tid + 256 * i;
            CP16(smem_u32(CBP(st, v >> 2, (v & 3) * 2)), src + v * 16);
        }
    };
    cpA(0); cpB(0); CPCOMMIT();
    float acc[4][4][4];
#pragma unroll
    for (int i = 0; i < 4; i++)
#pragma unroll
        for (int jn = 0; jn < 4; jn++)
#pragma unroll
            for (int r = 0; r < 4; r++) acc[i][jn][r] = 0.f;
    for (int kh = 0; kh < 16; kh++) {
        CPWAIT0(); __syncthreads();
        if (kh < 15) { cpA(kh + 1); cpB(kh + 1); CPCOMMIT(); }
        int cur = kh & 1;
#pragma unroll
        for (int ks = 0; ks < 2; ks++) {
            uint2 V[4];
#pragma unroll
            for (int nt = 0; nt < 4; nt++)
                V[nt] = *(uint2*)CBP(cur, wnn + nt * 8 + g, ks * 4 + tg);
#pragma unroll
            for (int mt = 0; mt < 4; mt++) {
                int m = wm + mt * 16 + g, w0 = ks * 8 + tg;
                uint32_t a0 = *(uint32_t*)CAP(cur, m, w0);
                uint32_t a2 = *(uint32_t*)CAP(cur, m, w0 + 4);
                uint32_t a1 = *(uint32_t*)CAP(cur, m + 8, w0);
                uint32_t a3 = *(uint32_t*)CAP(cur, m + 8, w0 + 4);
#pragma unroll
                for (int nt = 0; nt < 4; nt++)
                    mma_fp16(acc[mt][nt], a0, a1, a2, a3, V[nt].x, V[nt].y);
            }
        }
    }
#pragma unroll
    for (int mt = 0; mt < 4; mt++)
#pragma unroll
        for (int nt = 0; nt < 4; nt++) {
            const float* c = acc[mt][nt];
            int row = row0 + bm * 128 + wm + mt * 16 + g;
            int col = 128 + wnn + nt * 8 + 2 * tg;
            *(float2*)(dOut + (size_t)row * 256 + col) = make_float2(c[0], c[1]);
            *(float2*)(dOut + (size_t)(row + 8) * 256 + col) = make_float2(c[2], c[3]);
        }
}

// ---------- launch ----------
extern "C" void kernel_launch(void* const* d_in, const int* in_sizes, int n_in,
                              void* d_out, int out_size) {
    const float* center = (const float*)d_in[0];
    const float* nbr    = (const float*)d_in[1];
    const float* ew     = (const float*)d_in[2];
    const float* Wc     = (const float*)d_in[3];
    const float* Wn     = (const float*)d_in[4];
    const float* Wv     = (const float*)d_in[5];
    const float* Wo     = (const float*)d_in[6];
    const float* Wco    = (const float*)d_in[7];
    float* out = (float*)d_out;
    const int B = in_sizes[0] / 256;
    const int CH = B / NC;

    cudaFuncSetAttribute(k_front0, cudaFuncAttributeMaxDynamicSharedMemorySize, F0SMEM);
    cudaFuncSetAttribute(k_cout, cudaFuncAttributeMaxDynamicSharedMemorySize, COSMEM);
    cudaFuncSetAttribute(k_ctx, cudaFuncAttributeMaxDynamicSharedMemorySize, CSMEM);
    cudaFuncSetAttribute(k_prep_b3, cudaFuncAttributeMaxDynamicSharedMemorySize, P3_SMEM);

    k_prep_b0<<<64, 256>>>(Wc, Wco);
    k_prep_bn<<<32, 256>>>(Wn);
    k_prep_b3<<<16, 256, P3_SMEM>>>(Wo, Wv);
    cudaEventRecord(g_evP, 0);

    cudaStreamWaitEvent(g_s2, g_evP, 0);
    k_cout<<<B / 128, 256, COSMEM, g_s2>>>(center, out);

    for (int c = 0; c < NC; c++) {
        const int row0 = c * CH;
        k_front0<<<CH / 128, 256, F0SMEM>>>(center, row0);
        cudaEventRecord(g_evA[c], 0);
        cudaStreamWaitEvent(g_s1, g_evA[c], 0);
        k_attn<<<CH, 128, 0, g_s1>>>(nbr, ew, row0);
        cudaEventRecord(g_evN[c], g_s1);
        cudaStreamWaitEvent(g_s2, g_evN[c], 0);
        k_ctx<<<CH / 128, 256, CSMEM, g_s2>>>(out, row0);
    }
    cudaEventRecord(g_evEnd, g_s2);
    cudaStreamWaitEvent(0, g_evEnd, 0);
}

// round 17
// speedup vs baseline: 1.1712x; 1.0195x over previous
#include <cuda_runtime.h>
#include <cuda_fp16.h>
#include <cstdint>

#define BMAX 131072
#define NC   4

__device__ uint32_t g_qwh[(size_t)BMAX * 256];
__device__ uint2    g_wn[(size_t)BMAX * 128];
__device__ uint2    g_b0[2 * 8 * 128 * 8];
__device__ uint2    g_bn[4 * 2 * 128 * 8];
__device__ uint2    g_b3[16 * 128 * 8];

static cudaStream_t g_s1, g_s2;
static cudaEvent_t g_evA[NC], g_evN[NC], g_evP, g_evEnd;
namespace {
struct SInit {
    SInit() {
        cudaStreamCreateWithFlags(&g_s1, cudaStreamNonBlocking);
        cudaStreamCreateWithFlags(&g_s2, cudaStreamNonBlocking);
        for (int i = 0; i < NC; i++) {
            cudaEventCreateWithFlags(&g_evA[i], cudaEventDisableTiming);
            cudaEventCreateWithFlags(&g_evN[i], cudaEventDisableTiming);
        }
        cudaEventCreateWithFlags(&g_evP, cudaEventDisableTiming);
        cudaEventCreateWithFlags(&g_evEnd, cudaEventDisableTiming);
    }
};
SInit g_sinit;
}

__device__ __forceinline__ uint32_t smem_u32(const void* p) {
    uint32_t a;
    asm("{ .reg .u64 t; cvta.to.shared.u64 t, %1; cvt.u32.u64 %0, t; }" : "=r"(a) : "l"(p));
    return a;
}
__device__ __forceinline__ uint32_t hpack(float a, float b) {
    __half2 h = __floats2half2_rn(a, b);
    return *reinterpret_cast<uint32_t*>(&h);
}
__device__ __forceinline__ void mma_fp16(float* c, uint32_t a0, uint32_t a1,
                                         uint32_t a2, uint32_t a3, uint32_t b0, uint32_t b1) {
    asm volatile(
        "mma.sync.aligned.m16n8k16.row.col.f32.f16.f16.f32 "
        "{%0,%1,%2,%3},{%4,%5,%6,%7},{%8,%9},{%0,%1,%2,%3};\n"
        : "+f"(c[0]), "+f"(c[1]), "+f"(c[2]), "+f"(c[3])
        : "r"(a0), "r"(a1), "r"(a2), "r"(a3), "r"(b0), "r"(b1));
}
#define CP16(dst, src) \
    asm volatile("cp.async.cg.shared.global [%0], [%1], 16;\n" :: "r"(dst), "l"(src) : "memory")
#define CPCOMMIT() asm volatile("cp.async.commit_group;\n" ::: "memory")
#define CPWAIT0()  asm volatile("cp.async.wait_group 0;\n" ::: "memory")

// ---------- preps ----------
__global__ void k_prep_b0(const float* __restrict__ Wc, const float* __restrict__ Wco) {
    int idx = blockIdx.x * 256 + threadIdx.x;
    if (idx >= 2 * 8 * 128 * 8) return;
    int j = idx & 7, n = (idx >> 3) & 127, kh = (idx >> 10) & 7, nt = idx >> 13;
    int ks = j >> 2, tg = j & 3;
    int k0 = kh * 32 + ks * 16 + 2 * tg;
    const float* s = nt ? Wco : Wc;
    g_b0[idx] = make_uint2(hpack(s[n * 256 + k0], s[n * 256 + k0 + 1]),
                           hpack(s[n * 256 + k0 + 8], s[n * 256 + k0 + 9]));
}
__global__ void k_prep_bn(const float* __restrict__ Wn) {
    int idx = blockIdx.x * 256 + threadIdx.x;
    if (idx >= 4 * 2 * 128 * 8) return;
    int j = idx & 7, n = (idx >> 3) & 127, kh = (idx >> 10) & 1, nt = idx >> 11;
    int col = nt * 128 + n;
    int h = col >> 8, j2 = col & 255;
    int ks = j >> 2, tg = j & 3;
    int a0 = kh * 32 + ks * 16 + 2 * tg;
    g_bn[idx] = make_uint2(
        hpack(Wn[(h * 64 + a0) * 256 + j2], Wn[(h * 64 + a0 + 1) * 256 + j2]),
        hpack(Wn[(h * 64 + a0 + 8) * 256 + j2], Wn[(h * 64 + a0 + 9) * 256 + j2]));
}
#define P3_WO   0
#define P3_WV   (128 * 132 * 4)
#define P3_PART (P3_WV + 128 * 36 * 4)
#define P3_SMEM (P3_PART + 2 * 128 * 32 * 4)
__global__ void k_prep_b3(const float* __restrict__ Wo, const float* __restrict__ Wv) {
    extern __shared__ __align__(16) char sm3[];
    float* Wo_t = (float*)(sm3 + P3_WO);
    float* Wv_s = (float*)(sm3 + P3_WV);
    float* part = (float*)(sm3 + P3_PART);
    const int kh = blockIdx.x, h = kh >> 3, iwin = (kh * 32) & 255, tid = threadIdx.x;
    for (int i = tid; i < 4096; i += 256) {
        int n = i >> 5, d4 = i & 31;
        float4 x = *(const float4*)(Wo + n * 256 + h * 128 + d4 * 4);
        Wo_t[(d4 * 4 + 0) * 132 + n] = x.x; Wo_t[(d4 * 4 + 1) * 132 + n] = x.y;
        Wo_t[(d4 * 4 + 2) * 132 + n] = x.z; Wo_t[(d4 * 4 + 3) * 132 + n] = x.w;
    }
    for (int i = tid; i < 1024; i += 256) {
        int d = i >> 3, i4 = i & 7;
        *(float4*)&Wv_s[d * 36 + i4 * 4] = *(const float4*)(Wv + (h * 128 + d) * 256 + iwin + i4 * 4);
    }
    __syncthreads();
    {
        int n = tid & 127, hf = tid >> 7;
        float acc[32];
#pragma unroll
        for (int i = 0; i < 32; i++) acc[i] = 0.f;
        for (int d = hf * 64; d < hf * 64 + 64; d++) {
            float wo = Wo_t[d * 132 + n];
#pragma unroll
            for (int i4 = 0; i4 < 8; i4++) {
                float4 wv = *(const float4*)&Wv_s[d * 36 + i4 * 4];
                acc[i4 * 4 + 0] = fmaf(wo, wv.x, acc[i4 * 4 + 0]);
                acc[i4 * 4 + 1] = fmaf(wo, wv.y, acc[i4 * 4 + 1]);
                acc[i4 * 4 + 2] = fmaf(wo, wv.z, acc[i4 * 4 + 2]);
                acc[i4 * 4 + 3] = fmaf(wo, wv.w, acc[i4 * 4 + 3]);
            }
        }
#pragma unroll
        for (int i = 0; i < 32; i++) part[(hf * 128 + n) * 32 + i] = acc[i];
    }
    __syncthreads();
    for (int o = tid; o < 1024; o += 256) {
        int j = o & 7, n = o >> 3;
        int ks = j >> 2, tg = j & 3;
        int i0 = ks * 16 + 2 * tg;
        float v0 = part[n * 32 + i0] + part[(128 + n) * 32 + i0];
        float v1 = part[n * 32 + i0 + 1] + part[(128 + n) * 32 + i0 + 1];
        float v2 = part[n * 32 + i0 + 8] + part[(128 + n) * 32 + i0 + 8];
        float v3 = part[n * 32 + i0 + 9] + part[(128 + n) * 32 + i0 + 9];
        g_b3[kh * 1024 + n * 8 + j] = make_uint2(hpack(v0, v1), hpack(v2, v3));
    }
}

// ---------- k_front0: t (1-pass) then qW (1-pass, fp16 out) ----------
#define F0SMEM 73728
#define A1P(st, m, j) (smem + (st) * 12288 + (m) * 96 + (j) * 8)
#define B0P(st, n, j) (smem + 24576 + (st) * 12288 + (n) * 96 + (j) * 8)
#define TPP(p, m, j)  (smem + (p) * 12288 + (m) * 96 + (j) * 8)
#define G1P(kh, n, j) (smem + 49152 + (kh) * 12288 + (n) * 96 + (j) * 8)

__global__ __launch_bounds__(256) void k_front0(const float* __restrict__ Ain, int row0) {
    extern __shared__ __align__(16) char smem[];
    const int tid = threadIdx.x, lid = tid & 31, w = tid >> 5;
    const int g = lid >> 2, tg = lid & 3;
    const int wm = (w & 1) * 64, wnn = (w >> 1) * 32;
    const int bm = blockIdx.x;
    const float* Ab = Ain + (size_t)(row0 + bm * 128) * 256;
    const int arow = tid >> 1, aks = tid & 1;
    float4 f[2][4];
    auto loadA = [&](int kh, int sl) {
        const float* b = Ab + (size_t)arow * 256 + kh * 32 + aks * 16;
#pragma unroll
        for (int q = 0; q < 4; q++) f[sl][q] = *(const float4*)(b + q * 4);
    };
    auto sts1 = [&](int kh) {
        int st = kh & 1, sl = kh & 1;
        float4 f0 = f[sl][0], f1 = f[sl][1], f2 = f[sl][2], f3 = f[sl][3];
        *(uint2*)A1P(st, arow, aks * 4 + 0) = make_uint2(hpack(f0.x, f0.y), hpack(f2.x, f2.y));
        *(uint2*)A1P(st, arow, aks * 4 + 1) = make_uint2(hpack(f0.z, f0.w), hpack(f2.z, f2.w));
        *(uint2*)A1P(st, arow, aks * 4 + 2) = make_uint2(hpack(f1.x, f1.y), hpack(f3.x, f3.y));
        *(uint2*)A1P(st, arow, aks * 4 + 3) = make_uint2(hpack(f1.z, f1.w), hpack(f3.z, f3.w));
    };
    auto cpB0 = [&](int kh) {
        int st = kh & 1;
        const char* src = (const char*)g_b0 + (size_t)kh * 8192;
#pragma unroll
        for (int i = 0; i < 2; i++) {
            int v = tid + 256 * i;
            CP16(smem_u32(B0P(st, v >> 2, (v & 3) * 2)), src + v * 16);
        }
    };

    float acc[4][4][4];
#pragma unroll
    for (int i = 0; i < 4; i++)
#pragma unroll
        for (int jn = 0; jn < 4; jn++)
#pragma unroll
            for (int r = 0; r < 4; r++) acc[i][jn][r] = 0.f;

    cpB0(0); CPCOMMIT(); loadA(0, 0); sts1(0); loadA(1, 1);
    for (int kh = 0; kh < 8; kh++) {
        CPWAIT0(); __syncthreads();
        if (kh < 7) { cpB0(kh + 1); CPCOMMIT(); sts1(kh + 1); }
        if (kh < 6) loadA(kh + 2, kh & 1);
        int cur = kh & 1;
#pragma unroll
        for (int ks = 0; ks < 2; ks++) {
            uint2 V[4];
#pragma unroll
            for (int nt = 0; nt < 4; nt++)
                V[nt] = *(uint2*)B0P(cur, wnn + nt * 8 + g, ks * 4 + tg);
#pragma unroll
            for (int mt = 0; mt < 4; mt++) {
                uint2 U0 = *(uint2*)A1P(cur, wm + mt * 16 + g, ks * 4 + tg);
                uint2 U1 = *(uint2*)A1P(cur, wm + mt * 16 + g + 8, ks * 4 + tg);
#pragma unroll
                for (int nt = 0; nt < 4; nt++)
                    mma_fp16(acc[mt][nt], U0.x, U1.x, U0.y, U1.y, V[nt].x, V[nt].y);
            }
        }
    }
    __syncthreads();

#pragma unroll
    for (int mt = 0; mt < 4; mt++)
#pragma unroll
        for (int nt = 0; nt < 4; nt++) {
            int row = wm + mt * 16 + g, coll = wnn + nt * 8 + 2 * tg;
            int p = coll >> 5, ww = coll & 31;
            int ks2 = ww >> 4, w16 = ww & 15, hf = w16 >> 3, t2 = (w16 & 7) >> 1;
            int s = ks2 * 4 + t2;
            *(uint32_t*)(TPP(p, row, s) + hf * 4) = hpack(acc[mt][nt][0], acc[mt][nt][1]);
            *(uint32_t*)(TPP(p, row + 8, s) + hf * 4) = hpack(acc[mt][nt][2], acc[mt][nt][3]);
        }
    __syncthreads();

    auto cpG1 = [&](int nt2) {
        const char* src = (const char*)g_bn + (size_t)nt2 * 16384;
#pragma unroll
        for (int i = 0; i < 4; i++) {
            int v = tid + 256 * i;
            int kh = v >> 9, r = v & 511;
            CP16(smem_u32(G1P(kh, r >> 2, (r & 3) * 2)), src + v * 16);
        }
    };
    cpG1(0); CPCOMMIT();
    for (int nt2 = 0; nt2 < 4; nt2++) {
        CPWAIT0(); __syncthreads();
        int h = nt2 >> 1;
        float a2[4][4][4];
#pragma unroll
        for (int i = 0; i < 4; i++)
#pragma unroll
            for (int jn = 0; jn < 4; jn++)
#pragma unroll
                for (int r = 0; r < 4; r++) a2[i][jn][r] = 0.f;
#pragma unroll
        for (int kh2 = 0; kh2 < 2; kh2++) {
            int p = 2 * h + kh2;
#pragma unroll
            for (int ks = 0; ks < 2; ks++) {
                uint2 V[4];
#pragma unroll
                for (int n2 = 0; n2 < 4; n2++)
                    V[n2] = *(uint2*)G1P(kh2, wnn + n2 * 8 + g, ks * 4 + tg);
#pragma unroll
                for (int mt = 0; mt < 4; mt++) {
                    uint2 U0 = *(uint2*)TPP(p, wm + mt * 16 + g, ks * 4 + tg);
                    uint2 U1 = *(uint2*)TPP(p, wm + mt * 16 + g + 8, ks * 4 + tg);
#pragma unroll
                    for (int n2 = 0; n2 < 4; n2++)
                        mma_fp16(a2[mt][n2], U0.x, U1.x, U0.y, U1.y, V[n2].x, V[n2].y);
                }
            }
        }
        __syncthreads();
        if (nt2 < 3) { cpG1(nt2 + 1); CPCOMMIT(); }
#pragma unroll
        for (int mt = 0; mt < 4; mt++)
#pragma unroll
            for (int n2 = 0; n2 < 4; n2++) {
                const float* c = a2[mt][n2];
                int row = row0 + bm * 128 + wm + mt * 16 + g;
                int col = nt2 * 128 + wnn + n2 * 8 + 2 * tg;
                g_qwh[(size_t)row * 256 + (col >> 1)] = hpack(c[0], c[1]);
                g_qwh[(size_t)(row + 8) * 256 + (col >> 1)] = hpack(c[2], c[3]);
            }
    }
}

// ---------- k_cout: center_out = center @ Wco^T, 1-pass fp16, whole B ----------
#define COSMEM 49152
#define CAQ(st, m, j) (smem + (st) * 24576 + (m) * 96 + (j) * 8)
#define CBQ(st, n, j) (smem + 12288 + (st) * 24576 + (n) * 96 + (j) * 8)

__global__ __launch_bounds__(256) void k_cout(const float* __restrict__ Ain,
                                              float* __restrict__ dOut) {
    extern __shared__ __align__(16) char smem[];
    const int tid = threadIdx.x, lid = tid & 31, w = tid >> 5;
    const int g = lid >> 2, tg = lid & 3;
    const int wm = (w & 1) * 64, wnn = (w >> 1) * 32;
    const int bm = blockIdx.x;
    const float* Ab = Ain + (size_t)bm * 128 * 256;
    const int arow = tid >> 1, aks = tid & 1;
    float4 f[2][4];
    auto loadA = [&](int kh, int sl) {
        const float* b = Ab + (size_t)arow * 256 + kh * 32 + aks * 16;
#pragma unroll
        for (int q = 0; q < 4; q++) f[sl][q] = *(const float4*)(b + q * 4);
    };
    auto sts1 = [&](int kh) {
        int st = kh & 1, sl = kh & 1;
        float4 f0 = f[sl][0], f1 = f[sl][1], f2 = f[sl][2], f3 = f[sl][3];
        *(uint2*)CAQ(st, arow, aks * 4 + 0) = make_uint2(hpack(f0.x, f0.y), hpack(f2.x, f2.y));
        *(uint2*)CAQ(st, arow, aks * 4 + 1) = make_uint2(hpack(f0.z, f0.w), hpack(f2.z, f2.w));
        *(uint2*)CAQ(st, arow, aks * 4 + 2) = make_uint2(hpack(f1.x, f1.y), hpack(f3.x, f3.y));
        *(uint2*)CAQ(st, arow, aks * 4 + 3) = make_uint2(hpack(f1.z, f1.w), hpack(f3.z, f3.w));
    };
    auto cpB1 = [&](int kh) {
        int st = kh & 1;
        const char* src = (const char*)g_b0 + 65536 + (size_t)kh * 8192;
#pragma unroll
        for (int i = 0; i < 2; i++) {
            int v = tid + 256 * i;
            CP16(smem_u32(CBQ(st, v >> 2, (v & 3) * 2)), src + v * 16);
        }
    };
    float acc[4][4][4];
#pragma unroll
    for (int i = 0; i < 4; i++)
#pragma unroll
        for (int jn = 0; jn < 4; jn++)
#pragma unroll
            for (int r = 0; r < 4; r++) acc[i][jn][r] = 0.f;
    cpB1(0); CPCOMMIT(); loadA(0, 0); sts1(0); loadA(1, 1);
    for (int kh = 0; kh < 8; kh++) {
        CPWAIT0(); __syncthreads();
        if (kh < 7) { cpB1(kh + 1); CPCOMMIT(); sts1(kh + 1); }
        if (kh < 6) loadA(kh + 2, kh & 1);
        int cur = kh & 1;
#pragma unroll
        for (int ks = 0; ks < 2; ks++) {
            uint2 V[4];
#pragma unroll
            for (int nt = 0; nt < 4; nt++)
                V[nt] = *(uint2*)CBQ(cur, wnn + nt * 8 + g, ks * 4 + tg);
#pragma unroll
            for (int mt = 0; mt < 4; mt++) {
                uint2 U0 = *(uint2*)CAQ(cur, wm + mt * 16 + g, ks * 4 + tg);
                uint2 U1 = *(uint2*)CAQ(cur, wm + mt * 16 + g + 8, ks * 4 + tg);
#pragma unroll
                for (int nt = 0; nt < 4; nt++)
                    mma_fp16(acc[mt][nt], U0.x, U1.x, U0.y, U1.y, V[nt].x, V[nt].y);
            }
        }
    }
#pragma unroll
    for (int mt = 0; mt < 4; mt++)
#pragma unroll
        for (int nt = 0; nt < 4; nt++) {
            const float* c = acc[mt][nt];
            int row = bm * 128 + wm + mt * 16 + g;
            int coll = wnn + nt * 8 + 2 * tg;
            *(float2*)(dOut + (size_t)row * 256 + coll) = make_float2(c[0], c[1]);
            *(float2*)(dOut + (size_t)(row + 8) * 256 + coll) = make_float2(c[2], c[3]);
        }
}

// ---------- k_attn (R11-proven form) ----------
__global__ __launch_bounds__(128) void k_attn(const float* __restrict__ nb_g,
                                              const float* __restrict__ ew_g, int b0) {
    const int b = b0 + blockIdx.x;
    __shared__ uint2 nbh[16][68];
    __shared__ float qw_s[512];
    __shared__ float ews[16];
    __shared__ float sc[2][16];
    __shared__ float at[2][16];
    const int tid = threadIdx.x;
    const int k = tid >> 3, s = tid & 7;
    {
        uint2 u = ((const uint2*)(g_qwh + (size_t)b * 256))[tid];
        float2 a = __half22float2(*reinterpret_cast<__half2*>(&u.x));
        float2 bb = __half22float2(*reinterpret_cast<__half2*>(&u.y));
        *(float4*)&qw_s[tid * 4] = make_float4(a.x, a.y, bb.x, bb.y);
    }
    if (tid < 16) ews[tid] = ew_g[(size_t)b * 16 + tid];
    __syncthreads();
    const float4* nb4 = (const float4*)(nb_g + (size_t)b * 4096);
    float p0 = 0.f, p1 = 0.f;
#pragma unroll
    for (int j = 0; j < 8; j++) {
        int c4 = s + 8 * j;
        float4 x = nb4[k * 64 + c4];
        nbh[k][c4] = make_uint2(hpack(x.x, x.y), hpack(x.z, x.w));
        float4 q0 = *(const float4*)&qw_s[c4 * 4];
        float4 q1 = *(const float4*)&qw_s[256 + c4 * 4];
        p0 = fmaf(x.x, q0.x, p0); p0 = fmaf(x.y, q0.y, p0);
        p0 = fmaf(x.z, q0.z, p0); p0 = fmaf(x.w, q0.w, p0);
        p1 = fmaf(x.x, q1.x, p1); p1 = fmaf(x.y, q1.y, p1);
        p1 = fmaf(x.z, q1.z, p1); p1 = fmaf(x.w, q1.w, p1);
    }
#pragma unroll
    for (int o = 1; o <= 4; o <<= 1) {
        p0 += __shfl_xor_sync(0xffffffffu, p0, o);
        p1 += __shfl_xor_sync(0xffffffffu, p1, o);
    }
    if (s == 0) {
        sc[0][k] = p0 * 0.125f + ews[k];
        sc[1][k] = p1 * 0.125f + ews[k];
    }
    __syncthreads();
    if (tid < 32) {
        int hh = tid >> 4, kk = tid & 15;
        float v = sc[hh][kk];
        float m = v;
#pragma unroll
        for (int o = 8; o >= 1; o >>= 1)
            m = fmaxf(m, __shfl_xor_sync(0xffffffffu, m, o));
        float e = __expf(v - m);
        float sum = e;
#pragma unroll
        for (int o = 8; o >= 1; o >>= 1)
            sum += __shfl_xor_sync(0xffffffffu, sum, o);
        at[hh][kk] = e / sum;
    }
    __syncthreads();
    {
        int hh = tid >> 6, c2 = tid & 63;
        float4 acc = make_float4(0.f, 0.f, 0.f, 0.f);
#pragma unroll
        for (int kk = 0; kk < 16; kk++) {
            float wgt = at[hh][kk];
            uint2 u = nbh[kk][c2];
            float2 f0 = __half22float2(*reinterpret_cast<__half2*>(&u.x));
            float2 f1 = __half22float2(*reinterpret_cast<__half2*>(&u.y));
            acc.x = fmaf(wgt, f0.x, acc.x);
            acc.y = fmaf(wgt, f0.y, acc.y);
            acc.z = fmaf(wgt, f1.x, acc.z);
            acc.w = fmaf(wgt, f1.y, acc.w);
        }
        g_wn[(size_t)b * 128 + tid] = make_uint2(hpack(acc.x, acc.y), hpack(acc.z, acc.w));
    }
}

// ---------- k_ctx ----------
#define CSMEM 61440
#define CAP(st, m, wd) (smem + (st) * 30720 + (m) * 144 + (wd) * 4)
#define CBP(st, n, j)  (smem + (st) * 30720 + 18432 + (n) * 96 + (j) * 8)

__global__ __launch_bounds__(256) void k_ctx(float* __restrict__ dOut, int row0) {
    extern __shared__ __align__(16) char smem[];
    const int tid = threadIdx.x, lid = tid & 31, w = tid >> 5;
    const int g = lid >> 2, tg = lid & 3;
    const int wm = (w & 1) * 64, wnn = (w >> 1) * 32;
    const int bm = blockIdx.x;
    auto cpA = [&](int kh) {
        int st = kh & 1;
        const char* src = (const char*)g_wn + (size_t)(row0 + bm * 128) * 1024 + kh * 64;
#pragma unroll
        for (int i = 0; i < 2; i++) {
            int v = tid + 256 * i;
            CP16(smem_u32(CAP(st, v >> 2, (v & 3) * 4)), src + (size_t)(v >> 2) * 1024 + (v & 3) * 16);
        }
    };
    auto cpB = [&](int kh) {
        int st = kh & 1;
        const char* src = (const char*)g_b3 + (size_t)kh * 8192;
#pragma unroll
        for (int i = 0; i < 2; i++) {
            int v = tid + 256 * i;
            CP16(smem_u32(CBP(st, v >> 2, (v & 3) * 2)), src + v * 16);
        }
    };
    cpA(0); cpB(0); CPCOMMIT();
    float acc[4][4][4];
#pragma unroll
    for (int i = 0; i < 4; i++)
#pragma unroll
        for (int jn = 0; jn < 4; jn++)
#pragma unroll
            for (int r = 0; r < 4; r++) acc[i][jn][r] = 0.f;
    for (int kh = 0; kh < 16; kh++) {
        CPWAIT0(); __syncthreads();
        if (kh < 15) { cpA(kh + 1); cpB(kh + 1); CPCOMMIT(); }
        int cur = kh & 1;
#pragma unroll
        for (int ks = 0; ks < 2; ks++) {
            uint2 V[4];
#pragma unroll
            for (int nt = 0; nt < 4; nt++)
                V[nt] = *(uint2*)CBP(cur, wnn + nt * 8 + g, ks * 4 + tg);
#pragma unroll
            for (int mt = 0; mt < 4; mt++) {
                int m = wm + mt * 16 + g, w0 = ks * 8 + tg;
                uint32_t a0 = *(uint32_t*)CAP(cur, m, w0);
                uint32_t a2 = *(uint32_t*)CAP(cur, m, w0 + 4);
                uint32_t a1 = *(uint32_t*)CAP(cur, m + 8, w0);
                uint32_t a3 = *(uint32_t*)CAP(cur, m + 8, w0 + 4);
#pragma unroll
                for (int nt = 0; nt < 4; nt++)
                    mma_fp16(acc[mt][nt], a0, a1, a2, a3, V[nt].x, V[nt].y);
            }
        }
    }
#pragma unroll
    for (int mt = 0; mt < 4; mt++)
#pragma unroll
        for (int nt = 0; nt < 4; nt++) {
            const float* c = acc[mt][nt];
            int row = row0 + bm * 128 + wm + mt * 16 + g;
            int col = 128 + wnn + nt * 8 + 2 * tg;
            *(float2*)(dOut + (size_t)row * 256 + col) = make_float2(c[0], c[1]);
            *(float2*)(dOut + (size_t)(row + 8) * 256 + col) = make_float2(c[2], c[3]);
        }
}

// ---------- launch ----------
extern "C" void kernel_launch(void* const* d_in, const int* in_sizes, int n_in,
                              void* d_out, int out_size) {
    const float* center = (const float*)d_in[0];
    const float* nbr    = (const float*)d_in[1];
    const float* ew     = (const float*)d_in[2];
    const float* Wc     = (const float*)d_in[3];
    const float* Wn     = (const float*)d_in[4];
    const float* Wv     = (const float*)d_in[5];
    const float* Wo     = (const float*)d_in[6];
    const float* Wco    = (const float*)d_in[7];
    float* out = (float*)d_out;
    const int B = in_sizes[0] / 256;
    const int CH = B / NC;

    cudaFuncSetAttribute(k_front0, cudaFuncAttributeMaxDynamicSharedMemorySize, F0SMEM);
    cudaFuncSetAttribute(k_cout, cudaFuncAttributeMaxDynamicSharedMemorySize, COSMEM);
    cudaFuncSetAttribute(k_ctx, cudaFuncAttributeMaxDynamicSharedMemorySize, CSMEM);
    cudaFuncSetAttribute(k_prep_b3, cudaFuncAttributeMaxDynamicSharedMemorySize, P3_SMEM);

    k_prep_b0<<<64, 256>>>(Wc, Wco);
    k_prep_bn<<<32, 256>>>(Wn);
    k_prep_b3<<<16, 256, P3_SMEM>>>(Wo, Wv);
    cudaEventRecord(g_evP, 0);

    cudaStreamWaitEvent(g_s2, g_evP, 0);
    k_cout<<<B / 128, 256, COSMEM, g_s2>>>(center, out);

    for (int c = 0; c < NC; c++) {
        const int row0 = c * CH;
        k_front0<<<CH / 128, 256, F0SMEM>>>(center, row0);
        cudaEventRecord(g_evA[c], 0);
        cudaStreamWaitEvent(g_s1, g_evA[c], 0);
        k_attn<<<CH, 128, 0, g_s1>>>(nbr, ew, row0);
        cudaEventRecord(g_evN[c], g_s1);
        cudaStreamWaitEvent(g_s2, g_evN[c], 0);
        k_ctx<<<CH / 128, 256, CSMEM, g_s2>>>(out, row0);
    }
    cudaEventRecord(g_evEnd, g_s2);
    cudaStreamWaitEvent(0, g_evEnd, 0);
}